// round 1
// baseline (speedup 1.0000x reference)
#include <cuda_runtime.h>
#include <math.h>

#define NTOK 8192
#define DDIM 1024
#define NEXP 16
#define GRP 8          // tokens staged per iteration
#define TPB 64         // tokens per block
#define NBLK 128       // NTOK / TPB
#define NTHR 512

// ---- scratch (device globals: no allocation allowed) ----
__device__ float g_S[DDIM];          // column sums of h^2 ; zero at load, re-zeroed by moe_loss
__device__ float g_G[NEXP * NEXP];   // Gram matrix of expert outputs

// ============================================================================
// K1: fused router + shared/routed combine + S accumulation
//   grid = 128 blocks x 512 threads, 1 block/SM (heavy smem), single wave.
//   Per 8-token group:
//     stage h to smem -> logits (warp = 4 tokens x 2 experts, gate in regs)
//     -> warp-per-token top-2 router -> elementwise combine + h^2 accumulation
// ============================================================================
extern "C" __global__ void __launch_bounds__(NTHR, 1)
moe_main(const float* __restrict__ x,
         const float* __restrict__ gate_w,
         const float* __restrict__ gate_b,
         const float* __restrict__ sh_e,
         const float* __restrict__ rt_e,
         float* __restrict__ out)
{
    extern __shared__ float sm[];
    float* h_s     = sm;                        // GRP*DDIM      (32 KB)
    float* r_s     = h_s + GRP * DDIM;          // NEXP*DDIM     (64 KB)
    float* logit_s = r_s + NEXP * DDIM;         // GRP*NEXP
    float* w_s     = logit_s + GRP * NEXP;      // GRP*2
    int*   idx_s   = (int*)(w_s + GRP * 2);     // GRP*2

    const int tid  = threadIdx.x;
    const int warp = tid >> 5;
    const int lane = tid & 31;

    // stage routed experts into smem (read many times per token in combine)
    {
        const float4* src = (const float4*)rt_e;
        float4* dst = (float4*)r_s;
        for (int i = tid; i < NEXP * DDIM / 4; i += NTHR) dst[i] = src[i];
    }

    // per-thread d-slice (2 contiguous elements)
    const int d0 = 2 * tid;
    const float sh0 = sh_e[d0]     + sh_e[DDIM + d0];
    const float sh1 = sh_e[d0 + 1] + sh_e[DDIM + d0 + 1];

    // gate weights in registers: warp (th, ep) covers tokens [4th,4th+4) x experts {2ep, 2ep+1}
    const int th = warp >> 3;   // token half of the 8-token group
    const int ep = warp & 7;    // expert pair
    float ga[32], gb[32];
    #pragma unroll
    for (int i = 0; i < 32; i++) {
        ga[i] = gate_w[(2 * ep + 0) * DDIM + lane + 32 * i];
        gb[i] = gate_w[(2 * ep + 1) * DDIM + lane + 32 * i];
    }
    const float bia = gate_b[2 * ep];
    const float bib = gate_b[2 * ep + 1];

    __syncthreads();

    const int tok0 = blockIdx.x * TPB;
    float sA0 = 0.f, sA1 = 0.f;

    for (int g = 0; g < TPB; g += GRP) {
        // ---- stage 8 token rows of h (coalesced float4) ----
        {
            const float4* xs = (const float4*)(x + (size_t)(tok0 + g) * DDIM);
            float4* hd = (float4*)h_s;
            for (int i = tid; i < GRP * DDIM / 4; i += NTHR) hd[i] = xs[i];
        }
        __syncthreads();

        // ---- logits: 4 tokens x 2 experts per warp ----
        float a0 = 0, a1 = 0, a2 = 0, a3 = 0, b0 = 0, b1 = 0, b2 = 0, b3 = 0;
        const float* hb = h_s + th * 4 * DDIM + lane;
        #pragma unroll
        for (int i = 0; i < 32; i++) {
            float h0 = hb[0 * DDIM + 32 * i];
            float h1 = hb[1 * DDIM + 32 * i];
            float h2 = hb[2 * DDIM + 32 * i];
            float h3 = hb[3 * DDIM + 32 * i];
            float gva = ga[i], gvb = gb[i];
            a0 += gva * h0; a1 += gva * h1; a2 += gva * h2; a3 += gva * h3;
            b0 += gvb * h0; b1 += gvb * h1; b2 += gvb * h2; b3 += gvb * h3;
        }
        #pragma unroll
        for (int off = 16; off; off >>= 1) {
            a0 += __shfl_xor_sync(0xffffffffu, a0, off);
            a1 += __shfl_xor_sync(0xffffffffu, a1, off);
            a2 += __shfl_xor_sync(0xffffffffu, a2, off);
            a3 += __shfl_xor_sync(0xffffffffu, a3, off);
            b0 += __shfl_xor_sync(0xffffffffu, b0, off);
            b1 += __shfl_xor_sync(0xffffffffu, b1, off);
            b2 += __shfl_xor_sync(0xffffffffu, b2, off);
            b3 += __shfl_xor_sync(0xffffffffu, b3, off);
        }
        if (lane == 0) {
            logit_s[(th * 4 + 0) * NEXP + 2 * ep]     = a0 + bia;
            logit_s[(th * 4 + 1) * NEXP + 2 * ep]     = a1 + bia;
            logit_s[(th * 4 + 2) * NEXP + 2 * ep]     = a2 + bia;
            logit_s[(th * 4 + 3) * NEXP + 2 * ep]     = a3 + bia;
            logit_s[(th * 4 + 0) * NEXP + 2 * ep + 1] = b0 + bib;
            logit_s[(th * 4 + 1) * NEXP + 2 * ep + 1] = b1 + bib;
            logit_s[(th * 4 + 2) * NEXP + 2 * ep + 1] = b2 + bib;
            logit_s[(th * 4 + 3) * NEXP + 2 * ep + 1] = b3 + bib;
        }
        __syncthreads();

        // ---- router: warp t handles token t (top-2, lowest-index tie-break) ----
        if (warp < GRP) {
            float lg = (lane < NEXP) ? logit_s[warp * NEXP + lane] : -1e30f;
            float v1 = lg; int i1 = lane;
            #pragma unroll
            for (int off = 16; off; off >>= 1) {
                float ov = __shfl_xor_sync(0xffffffffu, v1, off);
                int   oi = __shfl_xor_sync(0xffffffffu, i1, off);
                if (ov > v1 || (ov == v1 && oi < i1)) { v1 = ov; i1 = oi; }
            }
            float lg2 = (lane == i1) ? -1e30f : lg;
            float v2 = lg2; int i2 = lane;
            #pragma unroll
            for (int off = 16; off; off >>= 1) {
                float ov = __shfl_xor_sync(0xffffffffu, v2, off);
                int   oi = __shfl_xor_sync(0xffffffffu, i2, off);
                if (ov > v2 || (ov == v2 && oi < i2)) { v2 = ov; i2 = oi; }
            }
            if (lane == 0) {
                // softmax denominator cancels in top-2 renormalization
                float w0 = 1.f / (1.f + __expf(v2 - v1));
                w_s[2 * warp]     = w0;
                w_s[2 * warp + 1] = 1.f - w0;
                idx_s[2 * warp]     = i1;
                idx_s[2 * warp + 1] = i2;
            }
        }
        __syncthreads();

        // ---- combine: out = h * (shared_sum_vec + w0*r_i0 + w1*r_i1); accumulate h^2 ----
        #pragma unroll
        for (int t = 0; t < GRP; t++) {
            float w0 = w_s[2 * t], w1 = w_s[2 * t + 1];
            int   i0 = idx_s[2 * t], i1x = idx_s[2 * t + 1];
            float2 hv = *(const float2*)(h_s + t * DDIM + d0);
            float2 r0 = *(const float2*)(r_s + i0  * DDIM + d0);
            float2 r1 = *(const float2*)(r_s + i1x * DDIM + d0);
            float c0 = sh0 + w0 * r0.x + w1 * r1.x;
            float c1 = sh1 + w0 * r0.y + w1 * r1.y;
            float2 o; o.x = hv.x * c0; o.y = hv.y * c1;
            *(float2*)(out + (size_t)(tok0 + g + t) * DDIM + d0) = o;
            sA0 += hv.x * hv.x;
            sA1 += hv.y * hv.y;
        }
        __syncthreads();   // h_s reused next iteration
    }

    atomicAdd(&g_S[d0],     sA0);
    atomicAdd(&g_S[d0 + 1], sA1);
}

// ============================================================================
// K2: Gram rows  G[e,f] = sum_d r_e[d] * r_f[d] * S[d]
//   grid = 16 blocks (one expert row each) x 256 threads
// ============================================================================
extern "C" __global__ void __launch_bounds__(256, 1)
moe_gram(const float* __restrict__ rt_e)
{
    extern __shared__ float sm2[];
    float* rs  = sm2;                   // NEXP*DDIM (64 KB)
    float* Ss  = rs + NEXP * DDIM;      // DDIM
    float* red = Ss + DDIM;             // 8*NEXP

    const int tid = threadIdx.x;
    for (int i = tid; i < NEXP * DDIM / 4; i += 256)
        ((float4*)rs)[i] = ((const float4*)rt_e)[i];
    for (int i = tid; i < DDIM; i += 256) Ss[i] = g_S[i];
    __syncthreads();

    const int e = blockIdx.x;
    float acc[NEXP];
    #pragma unroll
    for (int f = 0; f < NEXP; f++) acc[f] = 0.f;

    for (int d = tid; d < DDIM; d += 256) {
        float v = rs[e * DDIM + d] * Ss[d];
        #pragma unroll
        for (int f = 0; f < NEXP; f++) acc[f] += v * rs[f * DDIM + d];
    }

    const int wid = tid >> 5, lane = tid & 31;
    #pragma unroll
    for (int f = 0; f < NEXP; f++) {
        #pragma unroll
        for (int off = 16; off; off >>= 1)
            acc[f] += __shfl_xor_sync(0xffffffffu, acc[f], off);
    }
    if (lane == 0) {
        #pragma unroll
        for (int f = 0; f < NEXP; f++) red[wid * NEXP + f] = acc[f];
    }
    __syncthreads();
    if (tid < NEXP) {
        float s = 0.f;
        #pragma unroll
        for (int w = 0; w < 8; w++) s += red[w * NEXP + tid];
        g_G[e * NEXP + tid] = s;
    }
}

// ============================================================================
// K3: final diversity loss scalar; re-zero g_S for the next graph replay
// ============================================================================
extern "C" __global__ void moe_loss(float* __restrict__ out, int has_loss, int loss_idx)
{
    const int lane = threadIdx.x;   // 32 threads
    const int e = lane & 15;
    float n = sqrtf(g_G[e * NEXP + e]);
    n = fmaxf(n, 1e-8f);
    float s = 0.f;
    #pragma unroll
    for (int f = 0; f < NEXP; f++) {
        float nf = __shfl_sync(0xffffffffu, n, f);
        if (f != e) {
            float sim = g_G[e * NEXP + f] / (n * nf);
            sim = fminf(1.f, fmaxf(-1.f, sim));
            s += sim;
        }
    }
    if (lane >= 16) s = 0.f;
    #pragma unroll
    for (int off = 16; off; off >>= 1) s += __shfl_xor_sync(0xffffffffu, s, off);
    if (lane == 0 && has_loss)
        out[loss_idx] = s / (float)(NEXP * (NEXP - 1)) * 0.1f;

    // restore the S==0 invariant for the next iteration (graph replay safe)
    for (int i = lane; i < DDIM; i += 32) g_S[i] = 0.f;
}

// ============================================================================
extern "C" void kernel_launch(void* const* d_in, const int* in_sizes, int n_in,
                              void* d_out, int out_size)
{
    const float* x  = (const float*)d_in[0];
    const float* gw = (const float*)d_in[1];
    const float* gb = (const float*)d_in[2];
    const float* se = (const float*)d_in[3];
    const float* re = (const float*)d_in[4];
    float* out = (float*)d_out;

    const int SMEM1 = (GRP * DDIM + NEXP * DDIM + GRP * NEXP + 2 * GRP) * 4 + 2 * GRP * 4;
    const int SMEM2 = (NEXP * DDIM + DDIM + 8 * NEXP) * 4;

    cudaFuncSetAttribute((const void*)moe_main, cudaFuncAttributeMaxDynamicSharedMemorySize, SMEM1);
    cudaFuncSetAttribute((const void*)moe_gram, cudaFuncAttributeMaxDynamicSharedMemorySize, SMEM2);

    moe_main<<<NBLK, NTHR, SMEM1>>>(x, gw, gb, se, re, out);
    moe_gram<<<NEXP, 256, SMEM2>>>(re);

    int has_loss = (out_size > NTOK * DDIM) ? 1 : 0;
    moe_loss<<<1, 32>>>(out, has_loss, out_size - 1);
}